// round 14
// baseline (speedup 1.0000x reference)
#include <cuda_runtime.h>
#include <cstdint>
#include <cstddef>

// Problem constants
#define T_STEPS   101
#define B_SZ      16384
#define IN_DIM    40
#define HID       300
#define NPAD      320
#define OUT_DIM   12

#define WARPS_PER_BLK   18
#define THREADS_PER_BLK 576
#define ROWS_PER_BLK    18               // 1 row per warp
#define NUM_BLKS        ((B_SZ + ROWS_PER_BLK - 1) / ROWS_PER_BLK)  // 911
#define AL_STRIDE       304              // u16 entries; 4B-aligned per warp
#define TF              6                // time-fusion depth (proven optimum)

// Transposed, padded recurrent/ff weights (global, L2-resident: 384KB each)
__device__ float g_WhT[HID * NPAD];   // g_WhT[k*NPAD + i] = Wh[i*HID + k]
__device__ float g_W2T[HID * NPAD];

__global__ void prep_kernel(const float* __restrict__ Wh,
                            const float* __restrict__ W2) {
    int idx = blockIdx.x * blockDim.x + threadIdx.x;
    const int total = HID * NPAD;
    if (idx < total) {
        int k = idx / NPAD;
        int i = idx % NPAD;
        float wh = 0.0f, w2 = 0.0f;
        if (i < HID) {
            wh = Wh[i * HID + k];
            w2 = W2[i * HID + k];
        }
        g_WhT[idx] = wh;
        g_W2T[idx] = w2;
    }
}

// ---- packed f32x2 helpers ----
__device__ __forceinline__ unsigned long long pk2(float lo, float hi) {
    unsigned long long r;
    asm("mov.b64 %0, {%1, %2};" : "=l"(r) : "f"(lo), "f"(hi));
    return r;
}
__device__ __forceinline__ void upk2(unsigned long long v, float& lo, float& hi) {
    asm("mov.b64 {%0, %1}, %2;" : "=f"(lo), "=f"(hi) : "l"(v));
}
__device__ __forceinline__ void ffma2(unsigned long long& acc,
                                      unsigned long long a, unsigned long long b) {
    asm("fma.rn.f32x2 %0, %1, %2, %0;" : "+l"(acc) : "l"(a), "l"(b));
}
__device__ __forceinline__ void fadd2(unsigned long long& acc, unsigned long long a) {
    asm("add.rn.f32x2 %0, %0, %1;" : "+l"(acc) : "l"(a));
}
__device__ __forceinline__ unsigned long long fsub2(unsigned long long a,
                                                    unsigned long long b) {
    unsigned long long d;
    asm("sub.rn.f32x2 %0, %1, %2;" : "=l"(d) : "l"(a), "l"(b));
    return d;
}

// Slot layout per lane L (single row):
//  ull q=0: neurons (4L,   4L+1)    q=1: (4L+2,   4L+3)     [0..127]
//  ull q=2: (160+4L, 160+4L+1)      q=3: (160+4L+2, +3)     [160..287]
//  f32 s=0: 128+L  [128..159]       s=1: 288+L  [288..319]
__device__ __forceinline__ int qbase(int q, int L) {
    return (q < 2) ? (4 * L + 2 * q) : (160 + 4 * L + 2 * (q - 2));
}

// gather-add one weight row into (q[4], s[2])
__device__ __forceinline__ void gather_row(const float* __restrict__ w0, int L,
                                           unsigned long long* q, float* s) {
    ulonglong2 g0 = *(const ulonglong2*)(w0 + 4 * L);
    ulonglong2 g1 = *(const ulonglong2*)(w0 + 160 + 4 * L);
    float gs0 = w0[128 + L];
    float gs1 = w0[288 + L];
    fadd2(q[0], g0.x); fadd2(q[1], g0.y);
    fadd2(q[2], g1.x); fadd2(q[3], g1.y);
    s[0] += gs0; s[1] += gs1;
}

// gather loop over a spike list with paired u32 index reads
__device__ __forceinline__ void gather_list(const float* __restrict__ gw,
                                            const unsigned short* __restrict__ lst,
                                            int cn, int L,
                                            unsigned long long* q, float* s) {
    const unsigned* l32 = (const unsigned*)lst;
    int i = 0;
    for (; i + 2 <= cn; i += 2) {
        unsigned pr = l32[i >> 1];
        int i0 = (int)(pr & 0xffffu);
        int i1 = (int)(pr >> 16);
        gather_row(gw + i0 * NPAD, L, q, s);
        gather_row(gw + i1 * NPAD, L, q, s);
    }
    if (i < cn) gather_row(gw + (int)lst[i] * NPAD, L, q, s);
}

__global__ void __launch_bounds__(THREADS_PER_BLK, 1)
snn_kernel(const float* __restrict__ x,
           const float* __restrict__ W1,
           const float* __restrict__ b1,
           const float* __restrict__ bh,
           const float* __restrict__ b2,
           const float* __restrict__ W3,
           const float* __restrict__ b3,
           float* __restrict__ out) {
    extern __shared__ char smem_raw[];
    float* W1Ts = (float*)smem_raw;                 // [IN_DIM][NPAD]  51200 B
    float* bsum = W1Ts + IN_DIM * NPAD;             // [NPAD]
    float* b2s  = bsum + NPAD;                      // [NPAD]
    float* h1buf = b2s + NPAD;                      // [18 warps][TF-1][NPAD]
    unsigned short* al = (unsigned short*)(h1buf + WARPS_PER_BLK * (TF - 1) * NPAD);
    // al: [18 rows][AL_STRIDE] u16

    const int tid = threadIdx.x;

    for (int idx = tid; idx < IN_DIM * NPAD; idx += THREADS_PER_BLK) {
        int k = idx / NPAD;
        int h = idx % NPAD;
        W1Ts[idx] = (h < HID) ? W1[h * IN_DIM + k] : 0.0f;
    }
    for (int n = tid; n < NPAD; n += THREADS_PER_BLK) {
        bsum[n] = (n < HID) ? (b1[n] + bh[n]) : 0.0f;
        b2s[n]  = (n < HID) ? b2[n] : 0.0f;
    }
    __syncthreads();

    const int w = tid >> 5;
    const int L = tid & 31;
    int row = blockIdx.x * ROWS_PER_BLK + w;
    if (row >= B_SZ) row = B_SZ - 1;   // tail clamp: duplicate warps compute and
                                       // write identical values (deterministic)
    unsigned short* lst = al + w * AL_STRIDE;
    float* h1w = h1buf + w * ((TF - 1) * NPAD);  // [TF-1][NPAD]

    // layer-2 bias in registers
    ulonglong2 b2A, b2B;
    float b2S0, b2S1;
    {
        b2A = *(const ulonglong2*)(b2s + 4 * L);
        b2B = *(const ulonglong2*)(b2s + 160 + 4 * L);
        b2S0 = b2s[128 + L];
        b2S1 = b2s[288 + L];
    }

    // LIF states: 4 packed ulls + 2 scalars per layer (single row)
    unsigned long long v1q[4], v2q[4];
    float v1s[2], v2s[2];
    unsigned long long curq[4];
    float curs[2];
    unsigned c2[3];
    int cnt = 0;
#pragma unroll
    for (int q = 0; q < 4; q++) { v1q[q] = 0ull; v2q[q] = 0ull; }
    v1s[0] = v1s[1] = 0.0f;
    v2s[0] = v2s[1] = 0.0f;
    c2[0] = c2[1] = c2[2] = 0u;

    const unsigned long long HALF2 = 0x3F0000003F000000ull;
    const unsigned lt_mask = (1u << L) - 1u;

    const float* xptr = x + (size_t)row * IN_DIM;
    const size_t xstep = (size_t)B_SZ * IN_DIM;

#pragma unroll 1
    for (int t = 0; t < T_STEPS; t += TF) {
        // ---- x for TF steps ----
        float xa[TF], xb[TF];
#pragma unroll
        for (int s = 0; s < TF; s++) {
            const bool ok = (t + s < T_STEPS);
            xa[s] = ok ? xptr[s * xstep + L] : 0.0f;
            xb[s] = (ok && L < 8) ? xptr[s * xstep + 32 + L] : 0.0f;
        }
        xptr += TF * xstep;

        // ---- fused dense for TF steps, two 160-neuron half-passes ----
#pragma unroll
        for (int hp = 0; hp < 2; hp++) {
            const int hb = hp * 160;
            ulonglong2 cA[TF];
            float cS[TF];
            {
                ulonglong2 bA = *(const ulonglong2*)(bsum + hb + 4 * L);
                float bS = bsum[hb + 128 + L];
#pragma unroll
                for (int c = 0; c < TF; c++) { cA[c] = bA; cS[c] = bS; }
            }
#pragma unroll 4
            for (int k = 0; k < 32; k++) {
                const float* wr = W1Ts + k * NPAD + hb;
                ulonglong2 wA = *(const ulonglong2*)(wr + 4 * L);
                float wS = wr[128 + L];
#pragma unroll
                for (int c = 0; c < TF; c++) {
                    float xv = __shfl_sync(0xffffffffu, xa[c], k);
                    unsigned long long xp = pk2(xv, xv);
                    ffma2(cA[c].x, xp, wA.x);
                    ffma2(cA[c].y, xp, wA.y);
                    cS[c] = fmaf(xv, wS, cS[c]);
                }
            }
#pragma unroll
            for (int k = 0; k < 8; k++) {
                const float* wr = W1Ts + (32 + k) * NPAD + hb;
                ulonglong2 wA = *(const ulonglong2*)(wr + 4 * L);
                float wS = wr[128 + L];
#pragma unroll
                for (int c = 0; c < TF; c++) {
                    float xv = __shfl_sync(0xffffffffu, xb[c], k);
                    unsigned long long xp = pk2(xv, xv);
                    ffma2(cA[c].x, xp, wA.x);
                    ffma2(cA[c].y, xp, wA.y);
                    cS[c] = fmaf(xv, wS, cS[c]);
                }
            }
            // step t -> registers
            curq[2 * hp]     = cA[0].x;
            curq[2 * hp + 1] = cA[0].y;
            curs[hp]         = cS[0];
            // steps t+1..t+TF-1 -> smem stash
#pragma unroll
            for (int s = 1; s < TF; s++) {
                float* dst = h1w + (s - 1) * NPAD + hb;
                *(ulonglong2*)(dst + 4 * L) = cA[s];
                dst[128 + L] = cS[s];
            }
        }

        // ---- process steps t .. t+TF-1 ----
#pragma unroll 1
        for (int ss = 0; ss < TF; ss++) {
            if (t + ss >= T_STEPS) break;
            if (ss > 0) {
                const float* src = h1w + (ss - 1) * NPAD;
                ulonglong2 a0 = *(const ulonglong2*)(src + 4 * L);
                ulonglong2 a1 = *(const ulonglong2*)(src + 160 + 4 * L);
                curq[0] = a0.x; curq[1] = a0.y;
                curq[2] = a1.x; curq[3] = a1.y;
                curs[0] = src[128 + L];
                curs[1] = src[288 + L];
            }

            // ---- recurrent gathers (prev-step list) ----
            gather_list(g_WhT, lst, cnt, L, curq, curs);
            __syncwarp();

            // ---- LIF 1 + rebuild spike list ----
            {
                int nc = 0;
#pragma unroll
                for (int q = 0; q < 4; q++) {
                    unsigned long long d = fsub2(curq[q], v1q[q]);
                    unsigned long long vn = v1q[q];
                    ffma2(vn, d, HALF2);
                    float lo, hi;
                    upk2(vn, lo, hi);
                    bool s0 = (lo >= 1.0f), s1 = (hi >= 1.0f);
                    v1q[q] = pk2(s0 ? 0.0f : lo, s1 ? 0.0f : hi);
                    int nb = qbase(q, L);
                    unsigned m0 = __ballot_sync(0xffffffffu, s0);
                    if (s0) lst[nc + __popc(m0 & lt_mask)] = (unsigned short)nb;
                    nc += __popc(m0);
                    unsigned m1 = __ballot_sync(0xffffffffu, s1);
                    if (s1) lst[nc + __popc(m1 & lt_mask)] = (unsigned short)(nb + 1);
                    nc += __popc(m1);
                }
#pragma unroll
                for (int s = 0; s < 2; s++) {
                    float v = v1s[s] + (curs[s] - v1s[s]) * 0.5f;
                    bool sp = (v >= 1.0f);
                    v1s[s] = sp ? 0.0f : v;
                    int nb = s ? (288 + L) : (128 + L);
                    unsigned m = __ballot_sync(0xffffffffu, sp);
                    if (sp) lst[nc + __popc(m & lt_mask)] = (unsigned short)nb;
                    nc += __popc(m);
                }
                cnt = nc;
            }
            __syncwarp();

            // ---- layer 2: bias (registers) + gathers ----
            curq[0] = b2A.x; curq[1] = b2A.y;
            curq[2] = b2B.x; curq[3] = b2B.y;
            curs[0] = b2S0;  curs[1] = b2S1;
            gather_list(g_W2T, lst, cnt, L, curq, curs);

            // ---- LIF 2: packed update + 8-bit spike counters ----
#pragma unroll
            for (int q = 0; q < 4; q++) {
                unsigned long long d = fsub2(curq[q], v2q[q]);
                unsigned long long vn = v2q[q];
                ffma2(vn, d, HALF2);
                float lo, hi;
                upk2(vn, lo, hi);
                bool s0 = (lo >= 1.0f), s1 = (hi >= 1.0f);
                v2q[q] = pk2(s0 ? 0.0f : lo, s1 ? 0.0f : hi);
                int byte0 = 2 * (q & 1);
                c2[q >> 1] += s0 ? (1u << (8 * byte0)) : 0u;
                c2[q >> 1] += s1 ? (1u << (8 * (byte0 + 1))) : 0u;
            }
#pragma unroll
            for (int s = 0; s < 2; s++) {
                float v = v2s[s] + (curs[s] - v2s[s]) * 0.5f;
                bool sp = (v >= 1.0f);
                v2s[s] = sp ? 0.0f : v;
                c2[2] += sp ? (1u << (8 * s)) : 0u;
            }
        }
    }

    // ---- epilogue: out[row] = counts @ W3^T + 101*b3 ----
    {
        float acc[OUT_DIM];
#pragma unroll
        for (int o = 0; o < OUT_DIM; o++) acc[o] = 0.0f;
#pragma unroll
        for (int q = 0; q < 4; q++) {
#pragma unroll
            for (int e = 0; e < 2; e++) {
                int n = qbase(q, L) + e;
                float c = (float)((c2[q >> 1] >> (8 * (2 * (q & 1) + e))) & 255u);
                if (c != 0.0f) {
#pragma unroll
                    for (int o = 0; o < OUT_DIM; o++)
                        acc[o] = fmaf(c, W3[o * HID + n], acc[o]);
                }
            }
        }
#pragma unroll
        for (int s = 0; s < 2; s++) {
            int n = s ? (288 + L) : (128 + L);
            float c = (float)((c2[2] >> (8 * s)) & 255u);
            if (c != 0.0f && n < HID) {
#pragma unroll
                for (int o = 0; o < OUT_DIM; o++)
                    acc[o] = fmaf(c, W3[o * HID + n], acc[o]);
            }
        }
#pragma unroll
        for (int o = 0; o < OUT_DIM; o++) {
            float sv = acc[o];
            sv += __shfl_xor_sync(0xffffffffu, sv, 16);
            sv += __shfl_xor_sync(0xffffffffu, sv, 8);
            sv += __shfl_xor_sync(0xffffffffu, sv, 4);
            sv += __shfl_xor_sync(0xffffffffu, sv, 2);
            sv += __shfl_xor_sync(0xffffffffu, sv, 1);
            if (L == 0) out[row * OUT_DIM + o] = sv + 101.0f * b3[o];
        }
    }
}

extern "C" void kernel_launch(void* const* d_in, const int* in_sizes, int n_in,
                              void* d_out, int out_size) {
    const float* x  = (const float*)d_in[0];
    const float* W1 = (const float*)d_in[1];
    const float* b1 = (const float*)d_in[2];
    const float* Wh = (const float*)d_in[3];
    const float* bh = (const float*)d_in[4];
    const float* W2 = (const float*)d_in[5];
    const float* b2 = (const float*)d_in[6];
    const float* W3 = (const float*)d_in[7];
    const float* b3 = (const float*)d_in[8];
    float* out = (float*)d_out;

    {
        int total = HID * NPAD;
        int threads = 256;
        int blocks = (total + threads - 1) / threads;
        prep_kernel<<<blocks, threads>>>(Wh, W2);
    }

    size_t smem = (size_t)IN_DIM * NPAD * 4                   // W1Ts (51200)
                + NPAD * 4 + NPAD * 4                          // bsum, b2s (2560)
                + (size_t)WARPS_PER_BLK * (TF - 1) * NPAD * 4  // h1buf (115200)
                + (size_t)ROWS_PER_BLK * AL_STRIDE * 2;        // lists (10944)
    cudaFuncSetAttribute(snn_kernel, cudaFuncAttributeMaxDynamicSharedMemorySize,
                         (int)smem);
    snn_kernel<<<NUM_BLKS, THREADS_PER_BLK, smem>>>(x, W1, b1, bh, b2, W3, b3, out);
}

// round 15
// speedup vs baseline: 1.3543x; 1.3543x over previous
#include <cuda_runtime.h>
#include <cstdint>
#include <cstddef>

// Problem constants
#define T_STEPS   101
#define B_SZ      16384
#define IN_DIM    40
#define HID       300
#define NPAD      320
#define OUT_DIM   12

#define WARPS_PER_BLK   16
#define THREADS_PER_BLK 512
#define ROWS_PER_BLK    16               // 1 row per warp
#define NUM_BLKS        (B_SZ / ROWS_PER_BLK)   // 1024
#define AL_STRIDE       304              // u16 entries; 4B-aligned per warp
#define TF              6                // time-fusion depth (RF-optimal at 16 warps)

// Transposed, padded recurrent/ff weights (global, L2-resident: 384KB each)
__device__ float g_WhT[HID * NPAD];   // g_WhT[k*NPAD + i] = Wh[i*HID + k]
__device__ float g_W2T[HID * NPAD];

__global__ void prep_kernel(const float* __restrict__ Wh,
                            const float* __restrict__ W2) {
    int idx = blockIdx.x * blockDim.x + threadIdx.x;
    const int total = HID * NPAD;
    if (idx < total) {
        int k = idx / NPAD;
        int i = idx % NPAD;
        float wh = 0.0f, w2 = 0.0f;
        if (i < HID) {
            wh = Wh[i * HID + k];
            w2 = W2[i * HID + k];
        }
        g_WhT[idx] = wh;
        g_W2T[idx] = w2;
    }
}

// ---- packed f32x2 helpers ----
__device__ __forceinline__ unsigned long long pk2(float lo, float hi) {
    unsigned long long r;
    asm("mov.b64 %0, {%1, %2};" : "=l"(r) : "f"(lo), "f"(hi));
    return r;
}
__device__ __forceinline__ void upk2(unsigned long long v, float& lo, float& hi) {
    asm("mov.b64 {%0, %1}, %2;" : "=f"(lo), "=f"(hi) : "l"(v));
}
__device__ __forceinline__ void ffma2(unsigned long long& acc,
                                      unsigned long long a, unsigned long long b) {
    asm("fma.rn.f32x2 %0, %1, %2, %0;" : "+l"(acc) : "l"(a), "l"(b));
}
__device__ __forceinline__ void fadd2(unsigned long long& acc, unsigned long long a) {
    asm("add.rn.f32x2 %0, %0, %1;" : "+l"(acc) : "l"(a));
}
__device__ __forceinline__ unsigned long long fsub2(unsigned long long a,
                                                    unsigned long long b) {
    unsigned long long d;
    asm("sub.rn.f32x2 %0, %1, %2;" : "=l"(d) : "l"(a), "l"(b));
    return d;
}

// Slot layout per lane L (single row):
//  ull q=0: neurons (4L,   4L+1)    q=1: (4L+2,   4L+3)     [0..127]
//  ull q=2: (160+4L, 160+4L+1)      q=3: (160+4L+2, +3)     [160..287]
//  f32 s=0: 128+L  [128..159]       s=1: 288+L  [288..319]
__device__ __forceinline__ int qbase(int q, int L) {
    return (q < 2) ? (4 * L + 2 * q) : (160 + 4 * L + 2 * (q - 2));
}

// gather-add one weight row into (q[4], s[2])
__device__ __forceinline__ void gather_row(const float* __restrict__ w0, int L,
                                           unsigned long long* q, float* s) {
    ulonglong2 g0 = *(const ulonglong2*)(w0 + 4 * L);
    ulonglong2 g1 = *(const ulonglong2*)(w0 + 160 + 4 * L);
    float gs0 = w0[128 + L];
    float gs1 = w0[288 + L];
    fadd2(q[0], g0.x); fadd2(q[1], g0.y);
    fadd2(q[2], g1.x); fadd2(q[3], g1.y);
    s[0] += gs0; s[1] += gs1;
}

// fused: same spike index, gather W2T row into (q2,s2) AND WhT row into (qn,sn)
__device__ __forceinline__ void gather_row2(const float* __restrict__ w0,   // W2T row
                                            const float* __restrict__ u0,   // WhT row
                                            int L,
                                            unsigned long long* q2, float* s2,
                                            unsigned long long* qn, float* sn) {
    ulonglong2 a0 = *(const ulonglong2*)(w0 + 4 * L);
    ulonglong2 a1 = *(const ulonglong2*)(w0 + 160 + 4 * L);
    ulonglong2 c0 = *(const ulonglong2*)(u0 + 4 * L);
    ulonglong2 c1 = *(const ulonglong2*)(u0 + 160 + 4 * L);
    float as0 = w0[128 + L], as1 = w0[288 + L];
    float cs0 = u0[128 + L], cs1 = u0[288 + L];
    fadd2(q2[0], a0.x); fadd2(q2[1], a0.y);
    fadd2(q2[2], a1.x); fadd2(q2[3], a1.y);
    s2[0] += as0; s2[1] += as1;
    fadd2(qn[0], c0.x); fadd2(qn[1], c0.y);
    fadd2(qn[2], c1.x); fadd2(qn[3], c1.y);
    sn[0] += cs0; sn[1] += cs1;
}

// solo gather loop over a spike list (paired u32 index reads)
__device__ __forceinline__ void gather_list(const float* __restrict__ gw,
                                            const unsigned short* __restrict__ lst,
                                            int cn, int L,
                                            unsigned long long* q, float* s) {
    const unsigned* l32 = (const unsigned*)lst;
    int i = 0;
    for (; i + 2 <= cn; i += 2) {
        unsigned pr = l32[i >> 1];
        int i0 = (int)(pr & 0xffffu);
        int i1 = (int)(pr >> 16);
        gather_row(gw + i0 * NPAD, L, q, s);
        gather_row(gw + i1 * NPAD, L, q, s);
    }
    if (i < cn) gather_row(gw + (int)lst[i] * NPAD, L, q, s);
}

__global__ void __launch_bounds__(THREADS_PER_BLK, 1)
snn_kernel(const float* __restrict__ x,
           const float* __restrict__ W1,
           const float* __restrict__ b1,
           const float* __restrict__ bh,
           const float* __restrict__ b2,
           const float* __restrict__ W3,
           const float* __restrict__ b3,
           float* __restrict__ out) {
    extern __shared__ char smem_raw[];
    float* W1Ts = (float*)smem_raw;                 // [IN_DIM][NPAD]  51200 B
    float* bsum = W1Ts + IN_DIM * NPAD;             // [NPAD]
    float* b2s  = bsum + NPAD;                      // [NPAD]
    float* h1buf = b2s + NPAD;                      // [16 warps][TF-1][NPAD]
    unsigned short* al = (unsigned short*)(h1buf + WARPS_PER_BLK * (TF - 1) * NPAD);
    // al: [16 rows][AL_STRIDE] u16

    const int tid = threadIdx.x;

    for (int idx = tid; idx < IN_DIM * NPAD; idx += THREADS_PER_BLK) {
        int k = idx / NPAD;
        int h = idx % NPAD;
        W1Ts[idx] = (h < HID) ? W1[h * IN_DIM + k] : 0.0f;
    }
    for (int n = tid; n < NPAD; n += THREADS_PER_BLK) {
        bsum[n] = (n < HID) ? (b1[n] + bh[n]) : 0.0f;
        b2s[n]  = (n < HID) ? b2[n] : 0.0f;
    }
    __syncthreads();

    const int w = tid >> 5;
    const int L = tid & 31;
    const int row = blockIdx.x * ROWS_PER_BLK + w;
    unsigned short* lst = al + w * AL_STRIDE;
    float* h1w = h1buf + w * ((TF - 1) * NPAD);  // [TF-1][NPAD]

    // layer-2 bias in registers
    ulonglong2 b2A, b2B;
    float b2S0, b2S1;
    {
        b2A = *(const ulonglong2*)(b2s + 4 * L);
        b2B = *(const ulonglong2*)(b2s + 160 + 4 * L);
        b2S0 = b2s[128 + L];
        b2S1 = b2s[288 + L];
    }

    // LIF states: 4 packed ulls + 2 scalars per layer (single row)
    unsigned long long v1q[4], v2q[4];
    float v1s[2], v2s[2];
    unsigned long long curq[4];      // layer-1 current (this/next step)
    float curs[2];
    unsigned long long cur2q[4];     // layer-2 current
    float cur2s[2];
    unsigned c2[3];
    int cnt = 0;
#pragma unroll
    for (int q = 0; q < 4; q++) { v1q[q] = 0ull; v2q[q] = 0ull; }
    v1s[0] = v1s[1] = 0.0f;
    v2s[0] = v2s[1] = 0.0f;
    c2[0] = c2[1] = c2[2] = 0u;

    const unsigned long long HALF2 = 0x3F0000003F000000ull;
    const unsigned lt_mask = (1u << L) - 1u;

    const float* xptr = x + (size_t)row * IN_DIM;
    const size_t xstep = (size_t)B_SZ * IN_DIM;

#pragma unroll 1
    for (int t = 0; t < T_STEPS; t += TF) {
        // ---- x for TF steps ----
        float xa[TF], xb[TF];
#pragma unroll
        for (int s = 0; s < TF; s++) {
            const bool ok = (t + s < T_STEPS);
            xa[s] = ok ? xptr[s * xstep + L] : 0.0f;
            xb[s] = (ok && L < 8) ? xptr[s * xstep + 32 + L] : 0.0f;
        }
        xptr += TF * xstep;

        // ---- fused dense for TF steps, two 160-neuron half-passes ----
#pragma unroll
        for (int hp = 0; hp < 2; hp++) {
            const int hb = hp * 160;
            ulonglong2 cA[TF];
            float cS[TF];
            {
                ulonglong2 bA = *(const ulonglong2*)(bsum + hb + 4 * L);
                float bS = bsum[hb + 128 + L];
#pragma unroll
                for (int c = 0; c < TF; c++) { cA[c] = bA; cS[c] = bS; }
            }
#pragma unroll 4
            for (int k = 0; k < 32; k++) {
                const float* wr = W1Ts + k * NPAD + hb;
                ulonglong2 wA = *(const ulonglong2*)(wr + 4 * L);
                float wS = wr[128 + L];
#pragma unroll
                for (int c = 0; c < TF; c++) {
                    float xv = __shfl_sync(0xffffffffu, xa[c], k);
                    unsigned long long xp = pk2(xv, xv);
                    ffma2(cA[c].x, xp, wA.x);
                    ffma2(cA[c].y, xp, wA.y);
                    cS[c] = fmaf(xv, wS, cS[c]);
                }
            }
#pragma unroll
            for (int k = 0; k < 8; k++) {
                const float* wr = W1Ts + (32 + k) * NPAD + hb;
                ulonglong2 wA = *(const ulonglong2*)(wr + 4 * L);
                float wS = wr[128 + L];
#pragma unroll
                for (int c = 0; c < TF; c++) {
                    float xv = __shfl_sync(0xffffffffu, xb[c], k);
                    unsigned long long xp = pk2(xv, xv);
                    ffma2(cA[c].x, xp, wA.x);
                    ffma2(cA[c].y, xp, wA.y);
                    cS[c] = fmaf(xv, wS, cS[c]);
                }
            }
            // step t -> registers
            curq[2 * hp]     = cA[0].x;
            curq[2 * hp + 1] = cA[0].y;
            curs[hp]         = cS[0];
            // steps t+1..t+TF-1 -> smem stash
#pragma unroll
            for (int s = 1; s < TF; s++) {
                float* dst = h1w + (s - 1) * NPAD + hb;
                *(ulonglong2*)(dst + 4 * L) = cA[s];
                dst[128 + L] = cS[s];
            }
        }

        // ---- process steps t .. t+TF-1 ----
#pragma unroll 1
        for (int ss = 0; ss < TF; ss++) {
            if (t + ss >= T_STEPS) break;

            if (ss == 0) {
                // layer-1 gather for step t (list from previous block's last LIF1)
                gather_list(g_WhT, lst, cnt, L, curq, curs);
                __syncwarp();
            }
            // (ss > 0: curq/curs were pre-gathered by the fused loop below)

            // ---- LIF 1 + rebuild spike list ----
            {
                int nc = 0;
#pragma unroll
                for (int q = 0; q < 4; q++) {
                    unsigned long long d = fsub2(curq[q], v1q[q]);
                    unsigned long long vn = v1q[q];
                    ffma2(vn, d, HALF2);
                    float lo, hi;
                    upk2(vn, lo, hi);
                    bool s0 = (lo >= 1.0f), s1 = (hi >= 1.0f);
                    v1q[q] = pk2(s0 ? 0.0f : lo, s1 ? 0.0f : hi);
                    int nb = qbase(q, L);
                    unsigned m0 = __ballot_sync(0xffffffffu, s0);
                    if (s0) lst[nc + __popc(m0 & lt_mask)] = (unsigned short)nb;
                    nc += __popc(m0);
                    unsigned m1 = __ballot_sync(0xffffffffu, s1);
                    if (s1) lst[nc + __popc(m1 & lt_mask)] = (unsigned short)(nb + 1);
                    nc += __popc(m1);
                }
#pragma unroll
                for (int s = 0; s < 2; s++) {
                    float v = v1s[s] + (curs[s] - v1s[s]) * 0.5f;
                    bool sp = (v >= 1.0f);
                    v1s[s] = sp ? 0.0f : v;
                    int nb = s ? (288 + L) : (128 + L);
                    unsigned m = __ballot_sync(0xffffffffu, sp);
                    if (sp) lst[nc + __popc(m & lt_mask)] = (unsigned short)nb;
                    nc += __popc(m);
                }
                cnt = nc;
            }
            __syncwarp();

            // ---- layer-2 bias (registers) ----
            cur2q[0] = b2A.x; cur2q[1] = b2A.y;
            cur2q[2] = b2B.x; cur2q[3] = b2B.y;
            cur2s[0] = b2S0;  cur2s[1] = b2S1;

            const bool fuse = (ss + 1 < TF) && (t + ss + 1 < T_STEPS);
            if (fuse) {
                // preload next step's dense current from stash, then FUSED gather:
                // W2T row -> cur2 (layer 2, step ss), WhT row -> curq (layer 1, step ss+1)
                {
                    const float* src = h1w + ss * NPAD;
                    ulonglong2 a0 = *(const ulonglong2*)(src + 4 * L);
                    ulonglong2 a1 = *(const ulonglong2*)(src + 160 + 4 * L);
                    curq[0] = a0.x; curq[1] = a0.y;
                    curq[2] = a1.x; curq[3] = a1.y;
                    curs[0] = src[128 + L];
                    curs[1] = src[288 + L];
                }
                const unsigned* l32 = (const unsigned*)lst;
                int i = 0;
                for (; i + 2 <= cnt; i += 2) {
                    unsigned pr = l32[i >> 1];
                    int i0 = (int)(pr & 0xffffu);
                    int i1 = (int)(pr >> 16);
                    gather_row2(g_W2T + i0 * NPAD, g_WhT + i0 * NPAD, L,
                                cur2q, cur2s, curq, curs);
                    gather_row2(g_W2T + i1 * NPAD, g_WhT + i1 * NPAD, L,
                                cur2q, cur2s, curq, curs);
                }
                if (i < cnt) {
                    int i0 = (int)lst[i];
                    gather_row2(g_W2T + i0 * NPAD, g_WhT + i0 * NPAD, L,
                                cur2q, cur2s, curq, curs);
                }
            } else {
                // last step of block: solo W2T gather; list persists for the
                // next block's ss==0 WhT gather
                gather_list(g_W2T, lst, cnt, L, cur2q, cur2s);
            }
            __syncwarp();

            // ---- LIF 2: packed update + 8-bit spike counters ----
#pragma unroll
            for (int q = 0; q < 4; q++) {
                unsigned long long d = fsub2(cur2q[q], v2q[q]);
                unsigned long long vn = v2q[q];
                ffma2(vn, d, HALF2);
                float lo, hi;
                upk2(vn, lo, hi);
                bool s0 = (lo >= 1.0f), s1 = (hi >= 1.0f);
                v2q[q] = pk2(s0 ? 0.0f : lo, s1 ? 0.0f : hi);
                int byte0 = 2 * (q & 1);
                c2[q >> 1] += s0 ? (1u << (8 * byte0)) : 0u;
                c2[q >> 1] += s1 ? (1u << (8 * (byte0 + 1))) : 0u;
            }
#pragma unroll
            for (int s = 0; s < 2; s++) {
                float v = v2s[s] + (cur2s[s] - v2s[s]) * 0.5f;
                bool sp = (v >= 1.0f);
                v2s[s] = sp ? 0.0f : v;
                c2[2] += sp ? (1u << (8 * s)) : 0u;
            }
        }
    }

    // ---- epilogue: out[row] = counts @ W3^T + 101*b3 ----
    {
        float acc[OUT_DIM];
#pragma unroll
        for (int o = 0; o < OUT_DIM; o++) acc[o] = 0.0f;
#pragma unroll
        for (int q = 0; q < 4; q++) {
#pragma unroll
            for (int e = 0; e < 2; e++) {
                int n = qbase(q, L) + e;
                float c = (float)((c2[q >> 1] >> (8 * (2 * (q & 1) + e))) & 255u);
                if (c != 0.0f) {
#pragma unroll
                    for (int o = 0; o < OUT_DIM; o++)
                        acc[o] = fmaf(c, W3[o * HID + n], acc[o]);
                }
            }
        }
#pragma unroll
        for (int s = 0; s < 2; s++) {
            int n = s ? (288 + L) : (128 + L);
            float c = (float)((c2[2] >> (8 * s)) & 255u);
            if (c != 0.0f && n < HID) {
#pragma unroll
                for (int o = 0; o < OUT_DIM; o++)
                    acc[o] = fmaf(c, W3[o * HID + n], acc[o]);
            }
        }
#pragma unroll
        for (int o = 0; o < OUT_DIM; o++) {
            float sv = acc[o];
            sv += __shfl_xor_sync(0xffffffffu, sv, 16);
            sv += __shfl_xor_sync(0xffffffffu, sv, 8);
            sv += __shfl_xor_sync(0xffffffffu, sv, 4);
            sv += __shfl_xor_sync(0xffffffffu, sv, 2);
            sv += __shfl_xor_sync(0xffffffffu, sv, 1);
            if (L == 0) out[row * OUT_DIM + o] = sv + 101.0f * b3[o];
        }
    }
}

extern "C" void kernel_launch(void* const* d_in, const int* in_sizes, int n_in,
                              void* d_out, int out_size) {
    const float* x  = (const float*)d_in[0];
    const float* W1 = (const float*)d_in[1];
    const float* b1 = (const float*)d_in[2];
    const float* Wh = (const float*)d_in[3];
    const float* bh = (const float*)d_in[4];
    const float* W2 = (const float*)d_in[5];
    const float* b2 = (const float*)d_in[6];
    const float* W3 = (const float*)d_in[7];
    const float* b3 = (const float*)d_in[8];
    float* out = (float*)d_out;

    {
        int total = HID * NPAD;
        int threads = 256;
        int blocks = (total + threads - 1) / threads;
        prep_kernel<<<blocks, threads>>>(Wh, W2);
    }

    size_t smem = (size_t)IN_DIM * NPAD * 4                   // W1Ts (51200)
                + NPAD * 4 + NPAD * 4                          // bsum, b2s (2560)
                + (size_t)WARPS_PER_BLK * (TF - 1) * NPAD * 4  // h1buf (102400)
                + (size_t)ROWS_PER_BLK * AL_STRIDE * 2;        // lists (9728)
    cudaFuncSetAttribute(snn_kernel, cudaFuncAttributeMaxDynamicSharedMemorySize,
                         (int)smem);
    snn_kernel<<<NUM_BLKS, THREADS_PER_BLK, smem>>>(x, W1, b1, bh, b2, W3, b3, out);
}